// round 8
// baseline (speedup 1.0000x reference)
#include <cuda_runtime.h>
#include <math.h>

// Problem constants
#define TT 1000
#define BB 32
#define NN 2048
#define NC2 1024                 // uint2 (2-neuron) columns per batch
#define BN2 (BB * NC2)           // 32768 uint2 per timestep
#define NSEG 4
#define TSEG 250                 // timesteps per segment
#define UU 10                    // uint2 loads per prefetch group (250 = 25*10)
// Output layout (concatenated tuple, all f32):
#define OFF_FR 0
#define OFF_CV 65536
#define OFF_SY 131072
#define OFF_TS 131104
#define OFF_AN 196640

// Scratch (fully overwritten every launch; no init needed)
__device__ float g_pop_part[1024 * TSEG];   // [(b*4+seg)*8+chunk][tl]
__device__ int4  g_isi[NSEG * BB * NN];     // [seg][b][n] = {first,last,total,sumg2}
__device__ float g_active_part[256];        // per (b,chunk-of-256-neurons)

// ---------------------------------------------------------------------------
// Kernel 1: stream input once. grid = 32b x 4seg x 8chunk = 1024 blocks x 128.
// Each thread owns one uint2 column (2 neurons) for TSEG timesteps.
// ---------------------------------------------------------------------------
__device__ __forceinline__ void proc_group(
    const uint2* x, int tl0, int tbase, int lane, int w,
    int* last, int* first, int* total, int* sumg2, int (*pop_s)[TSEG])
{
    #pragma unroll
    for (int j = 0; j < UU; j++) {
        const int tl = tl0 + j;
        const int t  = tbase + tl;
        uint2 u = x[j];
        int s0 = (int)(u.x >> 29);   // 1.0f -> 1, 0.0f -> 0
        int s1 = (int)(u.y >> 29);
        unsigned psum = __reduce_add_sync(0xffffffffu, (unsigned)(s0 + s1));
        if (lane == 0) pop_s[w][tl] = (int)psum;

        if (s0) {
            if (last[0] >= 0) { int g = t - last[0]; sumg2[0] += g * g; }
            else              { first[0] = t; }
            last[0] = t; total[0]++;
        }
        if (s1) {
            if (last[1] >= 0) { int g = t - last[1]; sumg2[1] += g * g; }
            else              { first[1] = t; }
            last[1] = t; total[1]++;
        }
    }
}

__global__ __launch_bounds__(128, 6)
void spike_main(const float* __restrict__ in) {
    const int bid   = blockIdx.x;          // 0..1023
    const int b     = bid >> 5;            // batch
    const int seg   = (bid >> 3) & 3;      // time segment
    const int chunk = bid & 7;             // 128 uint2 columns each
    const int tid   = threadIdx.x;         // 0..127
    const int w     = tid >> 5;
    const int lane  = tid & 31;
    const int tbase = seg * TSEG;
    const int col   = (chunk << 7) | tid;  // uint2 column 0..1023

    __shared__ int pop_s[4][TSEG];         // 4 KB

    const uint2* p = (const uint2*)in + (size_t)tbase * BN2 + (size_t)b * NC2 + col;

    int last[2]  = {-1, -1};
    int first[2] = {-1, -1};
    int total[2] = {0, 0};
    int sumg2[2] = {0, 0};

    uint2 A[UU], Bf[UU];

    // Prime: group 0 -> A.  25 groups total: 12 ping-pong pairs + 1 tail.
    #pragma unroll
    for (int i = 0; i < UU; i++) A[i] = p[(size_t)i * BN2];

    #pragma unroll 1
    for (int gp = 0; gp < 12; gp++) {
        const int tA = gp * 2 * UU;
        const int tB = tA + UU;
        #pragma unroll
        for (int i = 0; i < UU; i++) Bf[i] = p[(size_t)(tB + i) * BN2];
        proc_group(A, tA, tbase, lane, w, last, first, total, sumg2, pop_s);
        const int tA2 = tB + UU;             // group 2gp+2 <= 24: always valid
        #pragma unroll
        for (int i = 0; i < UU; i++) A[i] = p[(size_t)(tA2 + i) * BN2];
        proc_group(Bf, tB, tbase, lane, w, last, first, total, sumg2, pop_s);
    }
    // tail group 24 (already in A)
    proc_group(A, 24 * UU, tbase, lane, w, last, first, total, sumg2, pop_s);

    // Per-neuron segment stats -> scratch (2 consecutive int4 per thread)
    const int nbase = (seg * BB + b) * NN + (col << 1);
    g_isi[nbase + 0] = make_int4(first[0], last[0], total[0], sumg2[0]);
    g_isi[nbase + 1] = make_int4(first[1], last[1], total[1], sumg2[1]);

    __syncthreads();
    // Reduce 4 warp rows -> per-block population partial
    #pragma unroll
    for (int r = 0; r < 2; r++) {
        int tl = tid + r * 128;
        if (tl < TSEG) {
            int s = pop_s[0][tl] + pop_s[1][tl] + pop_s[2][tl] + pop_s[3][tl];
            g_pop_part[bid * TSEG + tl] = (float)s;
        }
    }
}

// ---------------------------------------------------------------------------
// Kernel 2: merge 4 time segments per neuron. grid = 256 blocks x 256.
// ---------------------------------------------------------------------------
__global__ __launch_bounds__(256)
void spike_merge(float* __restrict__ out) {
    const int bid   = blockIdx.x;          // 0..255
    const int b     = bid >> 3;
    const int chunk = bid & 7;             // 256 neurons
    const int tid   = threadIdx.x;
    const int n     = (chunk << 8) | tid;
    const int w     = tid >> 5;
    const int lane  = tid & 31;

    __shared__ int active_s[8];

    int4 segs[NSEG];
    #pragma unroll
    for (int sg = 0; sg < NSEG; sg++)
        segs[sg] = g_isi[(sg * BB + b) * NN + n];

    int first = -1, last = -1, total = 0, sumg2 = 0;
    #pragma unroll
    for (int sg = 0; sg < NSEG; sg++) {
        int4 v = segs[sg];
        if (v.z > 0) {
            if (total > 0) { int g = v.x - last; sumg2 += g * g; }
            else           { first = v.x; }
            last   = v.y;
            total += v.z;
            sumg2 += v.w;
        }
    }

    const int idx = b * NN + n;
    float tot = (float)total;
    out[OFF_FR + idx] = tot / (TT * 0.001f);
    out[OFF_TS + idx] = tot;

    float cv = 0.0f;
    int cnt = total - 1;
    if (cnt >= 1) {
        float fc   = (float)cnt;
        float mean = (float)(last - first) / fc;
        float var  = ((float)sumg2 - fc * mean * mean) / fmaxf(fc - 1.0f, 1.0f);
        cv = sqrtf(fmaxf(var, 0.0f)) / fmaxf(mean, 1e-12f);
    }
    out[OFF_CV + idx] = cv;

    unsigned am = __ballot_sync(0xffffffffu, total > 0);
    if (lane == 0) active_s[w] = __popc(am);
    __syncthreads();
    if (tid == 0) {
        int a = 0;
        #pragma unroll
        for (int k = 0; k < 8; k++) a += active_s[k];
        g_active_part[bid] = (float)a;
    }
}

// ---------------------------------------------------------------------------
// Kernel 3: per-batch population autocorrelation + active count. grid = 32.
// ---------------------------------------------------------------------------
__global__ __launch_bounds__(256)
void spike_sync(float* __restrict__ out) {
    const int b    = blockIdx.x;    // 0..31
    const int tid  = threadIdx.x;
    const int w    = tid >> 5;
    const int lane = tid & 31;

    __shared__ float  pop[TT];
    __shared__ double red1[8], red2[8], redc[8];

    // Assemble pop[t]: sum the 8 chunk partials of the right (seg,tl)
    #pragma unroll
    for (int r = 0; r < 4; r++) {
        int t = tid + r * 256;
        if (t < TT) {
            int sg = t / TSEG;
            int tl = t - sg * TSEG;
            int rowb = (b * 4 + sg) * 8;
            float s = 0.0f;
            #pragma unroll
            for (int k = 0; k < 8; k++)
                s += g_pop_part[(rowb + k) * TSEG + tl];
            pop[t] = s;
        }
    }
    __syncthreads();

    // circular lag-1 autocorr: num = Sc - S1^2/T, den = S2 - S1^2/T
    double s1 = 0.0, s2 = 0.0, sc = 0.0;
    #pragma unroll
    for (int r = 0; r < 4; r++) {
        int t = tid + r * 256;
        if (t < TT) {
            double x  = (double)pop[t];
            int tp = (t == 0) ? (TT - 1) : (t - 1);
            double xp = (double)pop[tp];
            s1 += x;
            s2 += x * x;
            sc += x * xp;
        }
    }
    #pragma unroll
    for (int o = 16; o > 0; o >>= 1) {
        s1 += __shfl_down_sync(0xffffffffu, s1, o);
        s2 += __shfl_down_sync(0xffffffffu, s2, o);
        sc += __shfl_down_sync(0xffffffffu, sc, o);
    }
    if (lane == 0) { red1[w] = s1; red2[w] = s2; redc[w] = sc; }
    __syncthreads();
    if (tid == 0) {
        double S1 = 0.0, S2 = 0.0, Sc = 0.0;
        #pragma unroll
        for (int k = 0; k < 8; k++) { S1 += red1[k]; S2 += red2[k]; Sc += redc[k]; }
        double mt  = S1 * S1 / (double)TT;
        double num = Sc - mt;
        double den = S2 - mt;
        out[OFF_SY + b] = (den > 0.0) ? (float)(num / fmax(den, 1e-12)) : 0.0f;
        float a = 0.0f;
        #pragma unroll
        for (int k = 0; k < 8; k++) a += g_active_part[b * 8 + k];
        out[OFF_AN + b] = a;
    }
}

extern "C" void kernel_launch(void* const* d_in, const int* in_sizes, int n_in,
                              void* d_out, int out_size) {
    const float* in = (const float*)d_in[0];
    float* out = (float*)d_out;
    spike_main<<<1024, 128>>>(in);
    spike_merge<<<256, 256>>>(out);
    spike_sync<<<BB, 256>>>(out);
}

// round 9
// speedup vs baseline: 1.1073x; 1.1073x over previous
#include <cuda_runtime.h>
#include <math.h>

// Problem constants
#define TT 1000
#define BB 32
#define NN 2048
#define NC2 1024                 // uint2 (2-neuron) columns per batch
#define BN2 (BB * NC2)           // 32768 uint2 per timestep
#define NSEG 4
#define TSEG 250                 // timesteps per segment
#define UU 5                     // uint2 loads per prefetch group (250 = 50*5)
// Output layout (concatenated tuple, all f32):
#define OFF_FR 0
#define OFF_CV 65536
#define OFF_SY 131072
#define OFF_TS 131104
#define OFF_AN 196640

// Scratch (fully overwritten every launch; no init needed)
__device__ float g_pop_part[1024 * TSEG];   // [(b*4+seg)*8+chunk][tl]
__device__ int4  g_isi[NSEG * BB * NN];     // [seg][b][n] = {first,last,total,sumg2}
__device__ float g_active_part[256];        // per (b,chunk-of-256-neurons)

// ---------------------------------------------------------------------------
// Kernel 1: stream input once. grid = 32b x 4seg x 8chunk = 1024 blocks x 128.
// Each thread owns one uint2 column (2 neurons) for TSEG timesteps.
// ---------------------------------------------------------------------------
__device__ __forceinline__ void proc_group(
    const uint2* x, int tl0, int tbase, int lane, int w,
    int* last, int* first, int* total, int* sumg2, int (*pop_s)[TSEG])
{
    #pragma unroll
    for (int j = 0; j < UU; j++) {
        const int tl = tl0 + j;
        const int t  = tbase + tl;
        uint2 u = x[j];
        int s0 = (int)(u.x >> 29);   // 1.0f -> 1, 0.0f -> 0
        int s1 = (int)(u.y >> 29);
        unsigned psum = __reduce_add_sync(0xffffffffu, (unsigned)(s0 + s1));
        if (lane == 0) pop_s[w][tl] = (int)psum;

        if (s0) {
            if (last[0] >= 0) { int g = t - last[0]; sumg2[0] += g * g; }
            else              { first[0] = t; }
            last[0] = t; total[0]++;
        }
        if (s1) {
            if (last[1] >= 0) { int g = t - last[1]; sumg2[1] += g * g; }
            else              { first[1] = t; }
            last[1] = t; total[1]++;
        }
    }
}

__global__ __launch_bounds__(128, 8)
void spike_main(const float* __restrict__ in) {
    const int bid   = blockIdx.x;          // 0..1023
    const int b     = bid >> 5;            // batch
    const int seg   = (bid >> 3) & 3;      // time segment
    const int chunk = bid & 7;             // 128 uint2 columns each
    const int tid   = threadIdx.x;         // 0..127
    const int w     = tid >> 5;
    const int lane  = tid & 31;
    const int tbase = seg * TSEG;
    const int col   = (chunk << 7) | tid;  // uint2 column 0..1023

    __shared__ int pop_s[4][TSEG];         // 4 KB

    const uint2* p = (const uint2*)in + (size_t)tbase * BN2 + (size_t)b * NC2 + col;

    int last[2]  = {-1, -1};
    int first[2] = {-1, -1};
    int total[2] = {0, 0};
    int sumg2[2] = {0, 0};

    uint2 A[UU], Bf[UU];

    // Prime: group 0 -> A.  50 groups total: 25 ping-pong pairs.
    #pragma unroll
    for (int i = 0; i < UU; i++) A[i] = p[(size_t)i * BN2];

    #pragma unroll 1
    for (int gp = 0; gp < 25; gp++) {
        const int tA = gp * 2 * UU;
        const int tB = tA + UU;
        #pragma unroll
        for (int i = 0; i < UU; i++) Bf[i] = p[(size_t)(tB + i) * BN2];
        proc_group(A, tA, tbase, lane, w, last, first, total, sumg2, pop_s);
        if (gp < 24) {
            const int tA2 = tB + UU;
            #pragma unroll
            for (int i = 0; i < UU; i++) A[i] = p[(size_t)(tA2 + i) * BN2];
        }
        proc_group(Bf, tB, tbase, lane, w, last, first, total, sumg2, pop_s);
    }

    // Per-neuron segment stats -> scratch (2 consecutive int4 per thread)
    const int nbase = (seg * BB + b) * NN + (col << 1);
    g_isi[nbase + 0] = make_int4(first[0], last[0], total[0], sumg2[0]);
    g_isi[nbase + 1] = make_int4(first[1], last[1], total[1], sumg2[1]);

    __syncthreads();
    // Reduce 4 warp rows -> per-block population partial
    #pragma unroll
    for (int r = 0; r < 2; r++) {
        int tl = tid + r * 128;
        if (tl < TSEG) {
            int s = pop_s[0][tl] + pop_s[1][tl] + pop_s[2][tl] + pop_s[3][tl];
            g_pop_part[bid * TSEG + tl] = (float)s;
        }
    }
}

// ---------------------------------------------------------------------------
// Kernel 2 (fused): blocks 0..255 merge ISI segments per neuron;
// blocks 256..287 compute per-batch autocorrelation + active counts.
// NOTE: sync blocks read g_active_part written by merge blocks of the SAME
// launch — ordering is not guaranteed, so active counts go through merge
// blocks writing out[OFF_AN] partials? No: keep active via atomic-free path:
// sync blocks recompute active from g_isi directly (cheap, 2048 int4 loads).
// ---------------------------------------------------------------------------
__global__ __launch_bounds__(256)
void spike_tail(float* __restrict__ out) {
    const int gbid = blockIdx.x;
    const int tid  = threadIdx.x;
    const int w    = tid >> 5;
    const int lane = tid & 31;

    if (gbid < 256) {
        // ---------------- merge: 256 neurons per block ----------------
        const int b     = gbid >> 3;
        const int chunk = gbid & 7;
        const int n     = (chunk << 8) | tid;

        int4 segs[NSEG];
        #pragma unroll
        for (int sg = 0; sg < NSEG; sg++)
            segs[sg] = g_isi[(sg * BB + b) * NN + n];

        int first = -1, last = -1, total = 0, sumg2 = 0;
        #pragma unroll
        for (int sg = 0; sg < NSEG; sg++) {
            int4 v = segs[sg];
            if (v.z > 0) {
                if (total > 0) { int g = v.x - last; sumg2 += g * g; }
                else           { first = v.x; }
                last   = v.y;
                total += v.z;
                sumg2 += v.w;
            }
        }

        const int idx = b * NN + n;
        float tot = (float)total;
        out[OFF_FR + idx] = tot / (TT * 0.001f);
        out[OFF_TS + idx] = tot;

        float cv = 0.0f;
        int cnt = total - 1;
        if (cnt >= 1) {
            float fc   = (float)cnt;
            float mean = (float)(last - first) / fc;
            float var  = ((float)sumg2 - fc * mean * mean) / fmaxf(fc - 1.0f, 1.0f);
            cv = sqrtf(fmaxf(var, 0.0f)) / fmaxf(mean, 1e-12f);
        }
        out[OFF_CV + idx] = cv;
    } else {
        // ---------------- sync: one batch per block ----------------
        const int b = gbid - 256;      // 0..31

        __shared__ float  pop[TT];
        __shared__ double red1[8], red2[8], redc[8];
        __shared__ int    act_s[8];

        // Active neurons: total(n) > 0  <=>  any segment total > 0
        int act = 0;
        #pragma unroll 1
        for (int r = 0; r < 8; r++) {
            const int n = r * 256 + tid;
            int anyt = 0;
            #pragma unroll
            for (int sg = 0; sg < NSEG; sg++)
                anyt |= g_isi[(sg * BB + b) * NN + n].z;
            act += (anyt > 0);
        }
        act = (int)__reduce_add_sync(0xffffffffu, (unsigned)act);
        if (lane == 0) act_s[w] = act;

        // Assemble pop[t]
        #pragma unroll
        for (int r = 0; r < 4; r++) {
            int t = tid + r * 256;
            if (t < TT) {
                int sg = t / TSEG;
                int tl = t - sg * TSEG;
                int rowb = (b * 4 + sg) * 8;
                float s = 0.0f;
                #pragma unroll
                for (int k = 0; k < 8; k++)
                    s += g_pop_part[(rowb + k) * TSEG + tl];
                pop[t] = s;
            }
        }
        __syncthreads();

        // circular lag-1 autocorr: num = Sc - S1^2/T, den = S2 - S1^2/T
        double s1 = 0.0, s2 = 0.0, sc = 0.0;
        #pragma unroll
        for (int r = 0; r < 4; r++) {
            int t = tid + r * 256;
            if (t < TT) {
                double x  = (double)pop[t];
                int tp = (t == 0) ? (TT - 1) : (t - 1);
                double xp = (double)pop[tp];
                s1 += x;
                s2 += x * x;
                sc += x * xp;
            }
        }
        #pragma unroll
        for (int o = 16; o > 0; o >>= 1) {
            s1 += __shfl_down_sync(0xffffffffu, s1, o);
            s2 += __shfl_down_sync(0xffffffffu, s2, o);
            sc += __shfl_down_sync(0xffffffffu, sc, o);
        }
        if (lane == 0) { red1[w] = s1; red2[w] = s2; redc[w] = sc; }
        __syncthreads();
        if (tid == 0) {
            double S1 = 0.0, S2 = 0.0, Sc = 0.0;
            int a = 0;
            #pragma unroll
            for (int k = 0; k < 8; k++) {
                S1 += red1[k]; S2 += red2[k]; Sc += redc[k]; a += act_s[k];
            }
            double mt  = S1 * S1 / (double)TT;
            double num = Sc - mt;
            double den = S2 - mt;
            out[OFF_SY + b] = (den > 0.0) ? (float)(num / fmax(den, 1e-12)) : 0.0f;
            out[OFF_AN + b] = (float)a;
        }
    }
}

extern "C" void kernel_launch(void* const* d_in, const int* in_sizes, int n_in,
                              void* d_out, int out_size) {
    const float* in = (const float*)d_in[0];
    float* out = (float*)d_out;
    spike_main<<<1024, 128>>>(in);
    spike_tail<<<288, 256>>>(out);
}

// round 10
// speedup vs baseline: 1.1852x; 1.0704x over previous
#include <cuda_runtime.h>
#include <math.h>

// Problem constants
#define TT 1000
#define BB 32
#define NN 2048
#define NC2 1024                 // uint2 (2-neuron) columns per batch
#define BN2 (BB * NC2)           // 32768 uint2 per timestep
#define NSEG 4
#define TSEG 250                 // timesteps per segment
#define UU 5                     // uint2 loads per prefetch group (250 = 50*5)
// Output layout (concatenated tuple, all f32):
#define OFF_FR 0
#define OFF_CV 65536
#define OFF_SY 131072
#define OFF_TS 131104
#define OFF_AN 196640

// Scratch (fully overwritten every launch; no init needed)
__device__ float  g_pop_part[1024 * TSEG];  // [(b*4+seg)*8+chunk][tl]
__device__ int4   g_isi[NSEG * BB * NN];    // [seg][b][n] = {first,last,total,sumg2}
__device__ uchar2 g_tot[NSEG * BB * NC2];   // [seg][b][col] = per-neuron totals (<=250)

// ---------------------------------------------------------------------------
// Kernel 1: stream input once. grid = 32b x 4seg x 8chunk = 1024 blocks x 128.
// Each thread owns one uint2 column (2 neurons) for TSEG timesteps.
// ---------------------------------------------------------------------------
__device__ __forceinline__ void proc_group(
    const uint2* x, int tl0, int tbase, int lane, int w,
    int* last, int* first, int* total, int* sumg2, int (*pop_s)[TSEG])
{
    #pragma unroll
    for (int j = 0; j < UU; j++) {
        const int tl = tl0 + j;
        const int t  = tbase + tl;
        uint2 u = x[j];
        int s0 = (int)(u.x >> 29);   // 1.0f -> 1, 0.0f -> 0
        int s1 = (int)(u.y >> 29);
        unsigned psum = __reduce_add_sync(0xffffffffu, (unsigned)(s0 + s1));
        if (lane == 0) pop_s[w][tl] = (int)psum;

        if (s0) {
            if (last[0] >= 0) { int g = t - last[0]; sumg2[0] += g * g; }
            else              { first[0] = t; }
            last[0] = t; total[0]++;
        }
        if (s1) {
            if (last[1] >= 0) { int g = t - last[1]; sumg2[1] += g * g; }
            else              { first[1] = t; }
            last[1] = t; total[1]++;
        }
    }
}

__global__ __launch_bounds__(128, 8)
void spike_main(const float* __restrict__ in) {
    const int bid   = blockIdx.x;          // 0..1023
    const int b     = bid >> 5;            // batch
    const int seg   = (bid >> 3) & 3;      // time segment
    const int chunk = bid & 7;             // 128 uint2 columns each
    const int tid   = threadIdx.x;         // 0..127
    const int w     = tid >> 5;
    const int lane  = tid & 31;
    const int tbase = seg * TSEG;
    const int col   = (chunk << 7) | tid;  // uint2 column 0..1023

    __shared__ int pop_s[4][TSEG];         // 4 KB

    const uint2* p = (const uint2*)in + (size_t)tbase * BN2 + (size_t)b * NC2 + col;

    int last[2]  = {-1, -1};
    int first[2] = {-1, -1};
    int total[2] = {0, 0};
    int sumg2[2] = {0, 0};

    uint2 A[UU], Bf[UU];

    // Prime: group 0 -> A.  50 groups total: 25 ping-pong pairs.
    #pragma unroll
    for (int i = 0; i < UU; i++) A[i] = p[(size_t)i * BN2];

    #pragma unroll 1
    for (int gp = 0; gp < 25; gp++) {
        const int tA = gp * 2 * UU;
        const int tB = tA + UU;
        #pragma unroll
        for (int i = 0; i < UU; i++) Bf[i] = p[(size_t)(tB + i) * BN2];
        proc_group(A, tA, tbase, lane, w, last, first, total, sumg2, pop_s);
        if (gp < 24) {
            const int tA2 = tB + UU;
            #pragma unroll
            for (int i = 0; i < UU; i++) A[i] = p[(size_t)(tA2 + i) * BN2];
        }
        proc_group(Bf, tB, tbase, lane, w, last, first, total, sumg2, pop_s);
    }

    // Per-neuron segment stats -> scratch (2 consecutive int4 per thread)
    const int nbase = (seg * BB + b) * NN + (col << 1);
    g_isi[nbase + 0] = make_int4(first[0], last[0], total[0], sumg2[0]);
    g_isi[nbase + 1] = make_int4(first[1], last[1], total[1], sumg2[1]);
    // Compact per-neuron totals for the active-count path (<= 250 fits uchar)
    g_tot[(seg * BB + b) * NC2 + col] = make_uchar2((unsigned char)total[0],
                                                    (unsigned char)total[1]);

    __syncthreads();
    // Reduce 4 warp rows -> per-block population partial
    #pragma unroll
    for (int r = 0; r < 2; r++) {
        int tl = tid + r * 128;
        if (tl < TSEG) {
            int s = pop_s[0][tl] + pop_s[1][tl] + pop_s[2][tl] + pop_s[3][tl];
            g_pop_part[bid * TSEG + tl] = (float)s;
        }
    }
}

// ---------------------------------------------------------------------------
// Kernel 2 (fused tail): blocks 0..255 merge ISI segments per neuron;
// blocks 256..287 compute per-batch autocorrelation + active counts.
// Active counts come from g_tot (8 KB/block), not a g_isi rescan.
// ---------------------------------------------------------------------------
__global__ __launch_bounds__(256)
void spike_tail(float* __restrict__ out) {
    const int gbid = blockIdx.x;
    const int tid  = threadIdx.x;
    const int w    = tid >> 5;
    const int lane = tid & 31;

    if (gbid < 256) {
        // ---------------- merge: 256 neurons per block ----------------
        const int b     = gbid >> 3;
        const int chunk = gbid & 7;
        const int n     = (chunk << 8) | tid;

        int4 segs[NSEG];
        #pragma unroll
        for (int sg = 0; sg < NSEG; sg++)
            segs[sg] = g_isi[(sg * BB + b) * NN + n];

        int first = -1, last = -1, total = 0, sumg2 = 0;
        #pragma unroll
        for (int sg = 0; sg < NSEG; sg++) {
            int4 v = segs[sg];
            if (v.z > 0) {
                if (total > 0) { int g = v.x - last; sumg2 += g * g; }
                else           { first = v.x; }
                last   = v.y;
                total += v.z;
                sumg2 += v.w;
            }
        }

        const int idx = b * NN + n;
        float tot = (float)total;
        out[OFF_FR + idx] = tot / (TT * 0.001f);
        out[OFF_TS + idx] = tot;

        float cv = 0.0f;
        int cnt = total - 1;
        if (cnt >= 1) {
            float fc   = (float)cnt;
            float mean = (float)(last - first) / fc;
            float var  = ((float)sumg2 - fc * mean * mean) / fmaxf(fc - 1.0f, 1.0f);
            cv = sqrtf(fmaxf(var, 0.0f)) / fmaxf(mean, 1e-12f);
        }
        out[OFF_CV + idx] = cv;
    } else {
        // ---------------- sync: one batch per block ----------------
        const int b = gbid - 256;      // 0..31

        __shared__ float  pop[TT];
        __shared__ double red1[8], red2[8], redc[8];
        __shared__ int    act_s[8];

        // Active neurons from byte totals: per seg,b there are 2048 bytes
        // = 512 uints. Thread handles uints tid and tid+256; OR across segs,
        // count nonzero bytes. All 8 loads independent (full MLP).
        {
            const unsigned* tp = (const unsigned*)g_tot;
            unsigned v0 = 0, v1 = 0;
            #pragma unroll
            for (int sg = 0; sg < NSEG; sg++) {
                const unsigned* base = tp + (sg * BB + b) * 512;
                v0 |= base[tid];
                v1 |= base[tid + 256];
            }
            int act = (__popc(__vcmpgtu4(v0, 0u)) + __popc(__vcmpgtu4(v1, 0u))) >> 3;
            act = (int)__reduce_add_sync(0xffffffffu, (unsigned)act);
            if (lane == 0) act_s[w] = act;
        }

        // Assemble pop[t] (8 independent loads per t, 4 t per thread)
        #pragma unroll
        for (int r = 0; r < 4; r++) {
            int t = tid + r * 256;
            if (t < TT) {
                int sg = t / TSEG;
                int tl = t - sg * TSEG;
                int rowb = (b * 4 + sg) * 8;
                float s = 0.0f;
                #pragma unroll
                for (int k = 0; k < 8; k++)
                    s += g_pop_part[(rowb + k) * TSEG + tl];
                pop[t] = s;
            }
        }
        __syncthreads();

        // circular lag-1 autocorr: num = Sc - S1^2/T, den = S2 - S1^2/T
        double s1 = 0.0, s2 = 0.0, sc = 0.0;
        #pragma unroll
        for (int r = 0; r < 4; r++) {
            int t = tid + r * 256;
            if (t < TT) {
                double x  = (double)pop[t];
                int tp2 = (t == 0) ? (TT - 1) : (t - 1);
                double xp = (double)pop[tp2];
                s1 += x;
                s2 += x * x;
                sc += x * xp;
            }
        }
        #pragma unroll
        for (int o = 16; o > 0; o >>= 1) {
            s1 += __shfl_down_sync(0xffffffffu, s1, o);
            s2 += __shfl_down_sync(0xffffffffu, s2, o);
            sc += __shfl_down_sync(0xffffffffu, sc, o);
        }
        if (lane == 0) { red1[w] = s1; red2[w] = s2; redc[w] = sc; }
        __syncthreads();
        if (tid == 0) {
            double S1 = 0.0, S2 = 0.0, Sc = 0.0;
            int a = 0;
            #pragma unroll
            for (int k = 0; k < 8; k++) {
                S1 += red1[k]; S2 += red2[k]; Sc += redc[k]; a += act_s[k];
            }
            double mt  = S1 * S1 / (double)TT;
            double num = Sc - mt;
            double den = S2 - mt;
            out[OFF_SY + b] = (den > 0.0) ? (float)(num / fmax(den, 1e-12)) : 0.0f;
            out[OFF_AN + b] = (float)a;
        }
    }
}

extern "C" void kernel_launch(void* const* d_in, const int* in_sizes, int n_in,
                              void* d_out, int out_size) {
    const float* in = (const float*)d_in[0];
    float* out = (float*)d_out;
    spike_main<<<1024, 128>>>(in);
    spike_tail<<<288, 256>>>(out);
}

// round 11
// speedup vs baseline: 1.2222x; 1.0312x over previous
#include <cuda_runtime.h>
#include <math.h>

// Problem constants
#define TT 1000
#define BB 32
#define NN 2048
#define NC2 1024                 // uint2 (2-neuron) columns per batch
#define BN2 (BB * NC2)           // 32768 uint2 per timestep
#define NSEG 4
#define TSEG 250                 // timesteps per segment
#define UU 5                     // uint2 loads per prefetch group (250 = 50*5)
// Output layout (concatenated tuple, all f32):
#define OFF_FR 0
#define OFF_CV 65536
#define OFF_SY 131072
#define OFF_TS 131104
#define OFF_AN 196640

// Scratch (fully overwritten every launch; no init needed)
// Packed ISI per segment: x = first<<16 | last, y = total<<16 | sumg2
// (within a 250-step segment: first/last<=999, total<=250, sumg2<=62001<2^16)
__device__ float  g_pop_part[1024 * TSEG];  // [(b*4+seg)*8+chunk][tl]
__device__ uint2  g_isi[NSEG * BB * NN];    // packed per-segment ISI stats
__device__ uchar2 g_tot[NSEG * BB * NC2];   // [seg][b][col] per-neuron totals

// ---------------------------------------------------------------------------
// Kernel 1: stream input once. grid = 32b x 4seg x 8chunk = 1024 blocks x 128.
// Each thread owns one uint2 column (2 neurons) for TSEG timesteps.
// ---------------------------------------------------------------------------
__device__ __forceinline__ void proc_group(
    const uint2* x, int tl0, int tbase, int lane, int w,
    int* last, int* first, int* total, int* sumg2, int (*pop_s)[TSEG])
{
    #pragma unroll
    for (int j = 0; j < UU; j++) {
        const int tl = tl0 + j;
        const int t  = tbase + tl;
        uint2 u = x[j];
        int s0 = (int)(u.x >> 29);   // 1.0f -> 1, 0.0f -> 0
        int s1 = (int)(u.y >> 29);
        unsigned psum = __reduce_add_sync(0xffffffffu, (unsigned)(s0 + s1));
        if (lane == 0) pop_s[w][tl] = (int)psum;

        if (s0) {
            if (last[0] >= 0) { int g = t - last[0]; sumg2[0] += g * g; }
            else              { first[0] = t; }
            last[0] = t; total[0]++;
        }
        if (s1) {
            if (last[1] >= 0) { int g = t - last[1]; sumg2[1] += g * g; }
            else              { first[1] = t; }
            last[1] = t; total[1]++;
        }
    }
}

__global__ __launch_bounds__(128, 8)
void spike_main(const float* __restrict__ in) {
    const int bid   = blockIdx.x;          // 0..1023
    const int b     = bid >> 5;            // batch
    const int seg   = (bid >> 3) & 3;      // time segment
    const int chunk = bid & 7;             // 128 uint2 columns each
    const int tid   = threadIdx.x;         // 0..127
    const int w     = tid >> 5;
    const int lane  = tid & 31;
    const int tbase = seg * TSEG;
    const int col   = (chunk << 7) | tid;  // uint2 column 0..1023

    __shared__ int pop_s[4][TSEG];         // 4 KB

    const uint2* p = (const uint2*)in + (size_t)tbase * BN2 + (size_t)b * NC2 + col;

    int last[2]  = {-1, -1};
    int first[2] = {-1, -1};
    int total[2] = {0, 0};
    int sumg2[2] = {0, 0};

    uint2 A[UU], Bf[UU];

    // Prime: group 0 -> A.  50 groups total: 25 ping-pong pairs.
    #pragma unroll
    for (int i = 0; i < UU; i++) A[i] = __ldcs(p + (size_t)i * BN2);

    #pragma unroll 1
    for (int gp = 0; gp < 25; gp++) {
        const int tA = gp * 2 * UU;
        const int tB = tA + UU;
        #pragma unroll
        for (int i = 0; i < UU; i++) Bf[i] = __ldcs(p + (size_t)(tB + i) * BN2);
        proc_group(A, tA, tbase, lane, w, last, first, total, sumg2, pop_s);
        if (gp < 24) {
            const int tA2 = tB + UU;
            #pragma unroll
            for (int i = 0; i < UU; i++) A[i] = __ldcs(p + (size_t)(tA2 + i) * BN2);
        }
        proc_group(Bf, tB, tbase, lane, w, last, first, total, sumg2, pop_s);
    }

    // Packed per-neuron segment stats (2 consecutive uint2 per thread)
    const int nbase = (seg * BB + b) * NN + (col << 1);
    g_isi[nbase + 0] = make_uint2(
        (((unsigned)first[0] & 0xffffu) << 16) | ((unsigned)last[0] & 0xffffu),
        ((unsigned)total[0] << 16) | (unsigned)sumg2[0]);
    g_isi[nbase + 1] = make_uint2(
        (((unsigned)first[1] & 0xffffu) << 16) | ((unsigned)last[1] & 0xffffu),
        ((unsigned)total[1] << 16) | (unsigned)sumg2[1]);
    // Compact per-neuron totals for the active-count path
    g_tot[(seg * BB + b) * NC2 + col] = make_uchar2((unsigned char)total[0],
                                                    (unsigned char)total[1]);

    __syncthreads();
    // Reduce 4 warp rows -> per-block population partial
    #pragma unroll
    for (int r = 0; r < 2; r++) {
        int tl = tid + r * 128;
        if (tl < TSEG) {
            int s = pop_s[0][tl] + pop_s[1][tl] + pop_s[2][tl] + pop_s[3][tl];
            g_pop_part[bid * TSEG + tl] = (float)s;
        }
    }
}

// ---------------------------------------------------------------------------
// Kernel 2 (fused tail): blocks 0..255 merge ISI segments per neuron;
// blocks 256..287 compute per-batch autocorrelation + active counts.
// ---------------------------------------------------------------------------
__global__ __launch_bounds__(256)
void spike_tail(float* __restrict__ out) {
    const int gbid = blockIdx.x;
    const int tid  = threadIdx.x;
    const int w    = tid >> 5;
    const int lane = tid & 31;

    if (gbid < 256) {
        // ---------------- merge: 256 neurons per block ----------------
        const int b     = gbid >> 3;
        const int chunk = gbid & 7;
        const int n     = (chunk << 8) | tid;

        uint2 segs[NSEG];
        #pragma unroll
        for (int sg = 0; sg < NSEG; sg++)
            segs[sg] = g_isi[(sg * BB + b) * NN + n];

        int first = -1, last = -1, total = 0, sumg2 = 0;
        #pragma unroll
        for (int sg = 0; sg < NSEG; sg++) {
            int vt = (int)(segs[sg].y >> 16);          // segment total
            if (vt > 0) {
                int vf = (int)(segs[sg].x >> 16);       // segment first
                int vl = (int)(segs[sg].x & 0xffffu);   // segment last
                int vs = (int)(segs[sg].y & 0xffffu);   // segment sumg2
                if (total > 0) { int g = vf - last; sumg2 += g * g; }
                else           { first = vf; }
                last   = vl;
                total += vt;
                sumg2 += vs;
            }
        }

        const int idx = b * NN + n;
        float tot = (float)total;
        out[OFF_FR + idx] = tot / (TT * 0.001f);
        out[OFF_TS + idx] = tot;

        float cv = 0.0f;
        int cnt = total - 1;
        if (cnt >= 1) {
            float fc   = (float)cnt;
            float mean = (float)(last - first) / fc;
            float var  = ((float)sumg2 - fc * mean * mean) / fmaxf(fc - 1.0f, 1.0f);
            cv = sqrtf(fmaxf(var, 0.0f)) / fmaxf(mean, 1e-12f);
        }
        out[OFF_CV + idx] = cv;
    } else {
        // ---------------- sync: one batch per block ----------------
        const int b = gbid - 256;      // 0..31

        __shared__ float  pop[TT];
        __shared__ double red1[8], red2[8], redc[8];
        __shared__ int    act_s[8];

        // Active neurons from byte totals: 512 uints per (seg,b);
        // OR across segments, count nonzero bytes.
        {
            const unsigned* tp = (const unsigned*)g_tot;
            unsigned v0 = 0, v1 = 0;
            #pragma unroll
            for (int sg = 0; sg < NSEG; sg++) {
                const unsigned* base = tp + (sg * BB + b) * 512;
                v0 |= base[tid];
                v1 |= base[tid + 256];
            }
            int act = (__popc(__vcmpgtu4(v0, 0u)) + __popc(__vcmpgtu4(v1, 0u))) >> 3;
            act = (int)__reduce_add_sync(0xffffffffu, (unsigned)act);
            if (lane == 0) act_s[w] = act;
        }

        // Assemble pop[t]
        #pragma unroll
        for (int r = 0; r < 4; r++) {
            int t = tid + r * 256;
            if (t < TT) {
                int sg = t / TSEG;
                int tl = t - sg * TSEG;
                int rowb = (b * 4 + sg) * 8;
                float s = 0.0f;
                #pragma unroll
                for (int k = 0; k < 8; k++)
                    s += g_pop_part[(rowb + k) * TSEG + tl];
                pop[t] = s;
            }
        }
        __syncthreads();

        // circular lag-1 autocorr: num = Sc - S1^2/T, den = S2 - S1^2/T
        double s1 = 0.0, s2 = 0.0, sc = 0.0;
        #pragma unroll
        for (int r = 0; r < 4; r++) {
            int t = tid + r * 256;
            if (t < TT) {
                double x  = (double)pop[t];
                int tp2 = (t == 0) ? (TT - 1) : (t - 1);
                double xp = (double)pop[tp2];
                s1 += x;
                s2 += x * x;
                sc += x * xp;
            }
        }
        #pragma unroll
        for (int o = 16; o > 0; o >>= 1) {
            s1 += __shfl_down_sync(0xffffffffu, s1, o);
            s2 += __shfl_down_sync(0xffffffffu, s2, o);
            sc += __shfl_down_sync(0xffffffffu, sc, o);
        }
        if (lane == 0) { red1[w] = s1; red2[w] = s2; redc[w] = sc; }
        __syncthreads();
        if (tid == 0) {
            double S1 = 0.0, S2 = 0.0, Sc = 0.0;
            int a = 0;
            #pragma unroll
            for (int k = 0; k < 8; k++) {
                S1 += red1[k]; S2 += red2[k]; Sc += redc[k]; a += act_s[k];
            }
            double mt  = S1 * S1 / (double)TT;
            double num = Sc - mt;
            double den = S2 - mt;
            out[OFF_SY + b] = (den > 0.0) ? (float)(num / fmax(den, 1e-12)) : 0.0f;
            out[OFF_AN + b] = (float)a;
        }
    }
}

extern "C" void kernel_launch(void* const* d_in, const int* in_sizes, int n_in,
                              void* d_out, int out_size) {
    const float* in = (const float*)d_in[0];
    float* out = (float*)d_out;
    spike_main<<<1024, 128>>>(in);
    spike_tail<<<288, 256>>>(out);
}